// round 5
// baseline (speedup 1.0000x reference)
#include <cuda_runtime.h>
#include <cuda_bf16.h>

// Shapes (fixed for this problem): B=4, V=20000, D=64, R=64, E=640000
#define Bc   4
#define Dc   64
#define Rc   64
#define BD   256          // B*D
#define VMAX 20000
#define EMAX 640000
#define LN_EPS 1e-5f

// ---------------- device scratch (no allocations allowed) ----------------
__device__ float g_rel[Rc * BD];        // relation[r][b*64+d]   (64 KB)
__device__ int   g_cnt[VMAX + 1];
__device__ int   g_off[VMAX + 1];
__device__ int   g_cur[VMAX];
__device__ int   g_elist[EMAX];         // packed: src | (etype<<16)
__device__ float g_agg[(size_t)VMAX * BD];  // 20 MB

// ---------------- kernel A: relation table  zr = z @ Wz^T + bz ----------------
// grid = R blocks, 256 threads. g_rel[r][b*64+d] = bz[r*64+d] + sum_k z[b,k]*Wz[r*64+d, k]
__global__ void relation_kernel(const float* __restrict__ z,
                                const float* __restrict__ Wz,
                                const float* __restrict__ bz) {
    __shared__ float zs[BD];
    __shared__ float wzt[64 * 65];   // transposed, padded: wzt[k*65+d]
    int r = blockIdx.x, t = threadIdx.x;
    zs[t] = z[t];
    // coalesced gmem read, conflict-free smem write (stride 65)
    for (int idx = t; idx < 64 * 64; idx += 256) {
        int dd = idx >> 6, k = idx & 63;
        wzt[k * 65 + dd] = Wz[(r * 64 + dd) * 64 + k];
    }
    __syncthreads();
    int b = t >> 6, d = t & 63;
    float acc = bz[r * 64 + d];
#pragma unroll
    for (int k = 0; k < 64; k++)
        acc = fmaf(zs[b * 64 + k], wzt[k * 65 + d], acc);
    g_rel[r * BD + t] = acc;          // t == b*64+d
}

// ---------------- CSR build ----------------
__global__ void zero_kernel(int V) {
    int i = blockIdx.x * blockDim.x + threadIdx.x;
    if (i <= V) g_cnt[i] = 0;
}

__global__ void count_kernel(const int* __restrict__ ei, int E) {
    int e = blockIdx.x * blockDim.x + threadIdx.x;
    if (e < E) atomicAdd(&g_cnt[ei[e * 3 + 2]], 1);
}

// single-block exclusive scan over V counts (V <= 20480)
__global__ void scan_kernel(int V, int E) {
    __shared__ int sm[1024];
    int t = threadIdx.x;
    int P = (V + 1023) >> 10;
    int lo = t * P;
    int hi = lo + P; if (hi > V) hi = V;
    int s = 0;
    for (int i = lo; i < hi; i++) s += g_cnt[i];
    sm[t] = s;
    __syncthreads();
    for (int d = 1; d < 1024; d <<= 1) {
        int v = (t >= d) ? sm[t - d] : 0;
        __syncthreads();
        sm[t] += v;
        __syncthreads();
    }
    int run = sm[t] - s;   // exclusive prefix
    for (int i = lo; i < hi; i++) {
        g_off[i] = run;
        g_cur[i] = run;
        run += g_cnt[i];
    }
    if (t == 1023) g_off[V] = E;
}

__global__ void scatter_kernel(const int* __restrict__ ei, int E) {
    int e = blockIdx.x * blockDim.x + threadIdx.x;
    if (e >= E) return;
    int src = ei[e * 3 + 0];
    int et  = ei[e * 3 + 1];
    int dst = ei[e * 3 + 2];
    int p = atomicAdd(&g_cur[dst], 1);
    g_elist[p] = src | (et << 16);    // V<65536, R<65536
}

// ---------------- kernel C: aggregation (gather segment-sum) ----------------
// 64 threads per dst row (float4 per thread), 4 rows per 256-thread block.
// relation (64 KB) cached in dynamic smem; node gathers hit L2 (node set = 20 MB).
__global__ void agg_kernel(const float* __restrict__ x, int V) {
    extern __shared__ float rel_s[];  // 16384 floats = 64 KB
    for (int i = threadIdx.x; i < (Rc * BD) / 4; i += blockDim.x)
        ((float4*)rel_s)[i] = ((const float4*)g_rel)[i];
    __syncthreads();

    int ty = threadIdx.x >> 6;        // row slot 0..3
    int tx = threadIdx.x & 63;        // float4 lane: covers idx tx*4 = b*64+dbase
    int b = tx >> 4;
    int dbase = (tx << 2) & 63;
    const float* xb = x + (size_t)b * V * 64 + dbase;   // x[b][.][dbase]
    const float4* relp = (const float4*)(rel_s + tx * 4);

    for (int v = blockIdx.x * 4 + ty; v < V; v += gridDim.x * 4) {
        int s = g_off[v], e = g_off[v + 1];
        float4 acc = make_float4(0.f, 0.f, 0.f, 0.f);
#pragma unroll 4
        for (int i = s; i < e; i++) {
            int p = g_elist[i];
            int src = p & 0xFFFF;
            int et  = p >> 16;
            float4 nv = *(const float4*)(xb + src * 64);
            float4 rv = *(const float4*)((const float*)relp + et * BD);
            acc.x = fmaf(nv.x, rv.x, acc.x);
            acc.y = fmaf(nv.y, rv.y, acc.y);
            acc.z = fmaf(nv.z, rv.z, acc.z);
            acc.w = fmaf(nv.w, rv.w, acc.w);
        }
        *(float4*)(g_agg + (size_t)v * BD + tx * 4) = acc;
    }
}

// ---------------- kernel D: MLP (+beta*x, ReLU, LN, +x residual) ----------------
// 256 threads = one dst row (4 batches x 64 dims). Thread owns output column
// d' = tid&63 for batch b = tid>>6; both weight rows live in registers.
__global__ void __launch_bounds__(256) mlp_kernel(
    const float* __restrict__ x,
    const float* __restrict__ W1, const float* __restrict__ b1,
    const float* __restrict__ W2, const float* __restrict__ b2,
    const float* __restrict__ beta,
    const float* __restrict__ lnw, const float* __restrict__ lnb,
    float* __restrict__ out, int V)
{
    __shared__ float hsA[BD];
    __shared__ float hsB[BD];
    __shared__ float red[16];         // 8 warps x {sum, sumsq}
    int t = threadIdx.x;
    int b = t >> 6, dq = t & 63;
    int warp = t >> 5;

    float w1r[64], w2r[64];
#pragma unroll
    for (int i = 0; i < 64; i++) {
        w1r[i] = W1[dq * 64 + i];
        w2r[i] = W2[dq * 64 + i];
    }
    float b1r = b1[dq], b2r = b2[dq];
    float betar = beta[dq], lnwr = lnw[dq], lnbr = lnb[dq];

    const float* xb = x + (size_t)b * V * 64;
    float*       ob = out + (size_t)b * V * 64;

    for (int v = blockIdx.x; v < V; v += gridDim.x) {
        float xv = xb[v * 64 + dq];
        float h0 = g_agg[(size_t)v * BD + t] + betar * xv;
        hsA[t] = h0;
        __syncthreads();

        // h1 = relu(h0 @ W1^T + b1)
        float a1 = b1r;
        const float4* hp = (const float4*)(hsA + (b << 6));
#pragma unroll
        for (int i = 0; i < 16; i++) {
            float4 h4 = hp[i];
            a1 = fmaf(h4.x, w1r[4 * i + 0], a1);
            a1 = fmaf(h4.y, w1r[4 * i + 1], a1);
            a1 = fmaf(h4.z, w1r[4 * i + 2], a1);
            a1 = fmaf(h4.w, w1r[4 * i + 3], a1);
        }
        a1 = fmaxf(a1, 0.f);
        hsB[t] = a1;
        __syncthreads();

        // h2 = h1 @ W2^T + b2
        float a2 = b2r;
        const float4* hp2 = (const float4*)(hsB + (b << 6));
#pragma unroll
        for (int i = 0; i < 16; i++) {
            float4 h4 = hp2[i];
            a2 = fmaf(h4.x, w2r[4 * i + 0], a2);
            a2 = fmaf(h4.y, w2r[4 * i + 1], a2);
            a2 = fmaf(h4.z, w2r[4 * i + 2], a2);
            a2 = fmaf(h4.w, w2r[4 * i + 3], a2);
        }

        // LayerNorm over the 64 dims of this (b, v) row (64 threads = 2 warps)
        float s = a2, sq = a2 * a2;
#pragma unroll
        for (int o = 16; o; o >>= 1) {
            s  += __shfl_xor_sync(0xFFFFFFFFu, s,  o);
            sq += __shfl_xor_sync(0xFFFFFFFFu, sq, o);
        }
        if ((t & 31) == 0) { red[warp * 2] = s; red[warp * 2 + 1] = sq; }
        __syncthreads();
        float st  = red[4 * b + 0] + red[4 * b + 2];
        float sqt = red[4 * b + 1] + red[4 * b + 3];
        float mu  = st * (1.f / 64.f);
        float var = sqt * (1.f / 64.f) - mu * mu;
        float o = (a2 - mu) * rsqrtf(var + LN_EPS) * lnwr + lnbr + xv;
        ob[v * 64 + dq] = o;
        // next-iteration hsA write is safe: every thread has passed the red sync,
        // which postdates all hsA/hsB reads of this iteration.
    }
}

// ---------------- launch ----------------
extern "C" void kernel_launch(void* const* d_in, const int* in_sizes, int n_in,
                              void* d_out, int out_size) {
    const float* x    = (const float*)d_in[0];
    const float* z    = (const float*)d_in[1];
    const int*   ei   = (const int*)  d_in[2];
    // d_in[3] = r_index (unused by reference)
    const float* Wz   = (const float*)d_in[4];
    const float* bz   = (const float*)d_in[5];
    const float* W1   = (const float*)d_in[6];
    const float* b1   = (const float*)d_in[7];
    const float* W2   = (const float*)d_in[8];
    const float* b2   = (const float*)d_in[9];
    const float* beta = (const float*)d_in[10];
    const float* lnw  = (const float*)d_in[11];
    const float* lnb  = (const float*)d_in[12];
    float* out = (float*)d_out;

    int E = in_sizes[2] / 3;
    int V = in_sizes[0] / (Bc * Dc);

    relation_kernel<<<Rc, 256>>>(z, Wz, bz);
    zero_kernel<<<(V + 1 + 255) / 256, 256>>>(V);
    count_kernel<<<(E + 255) / 256, 256>>>(ei, E);
    scan_kernel<<<1, 1024>>>(V, E);
    scatter_kernel<<<(E + 255) / 256, 256>>>(ei, E);

    cudaFuncSetAttribute((const void*)agg_kernel,
                         cudaFuncAttributeMaxDynamicSharedMemorySize, 65536);
    agg_kernel<<<444, 256, 65536>>>(x, V);

    mlp_kernel<<<296, 256>>>(x, W1, b1, W2, b2, beta, lnw, lnb, out, V);
}

// round 6
// speedup vs baseline: 1.4520x; 1.4520x over previous
#include <cuda_runtime.h>
#include <cuda_bf16.h>

// Shapes (fixed for this problem): B=4, V=20000, D=64, R=64, E=640000
#define Bc   4
#define Dc   64
#define Rc   64
#define BD   256          // B*D
#define VMAX 20000
#define EMAX 640000
#define LN_EPS 1e-5f

// ---------------- device scratch (no allocations allowed) ----------------
__device__ float g_rel[Rc * BD];        // relation[r][b*64+d]   (64 KB)
__device__ int   g_cnt[VMAX + 1];       // zero-initialized; re-zeroed each run in scan_part3
__device__ int   g_off[VMAX + 1];
__device__ int   g_cur[VMAX];
__device__ int   g_elist[EMAX];         // packed: src | (etype<<16)
__device__ float g_agg[(size_t)VMAX * BD];  // 20 MB
__device__ int   g_bsum[256];
__device__ int   g_bbase[256];

// ---------------- packed f32x2 helpers (Blackwell FFMA2) ----------------
__device__ __forceinline__ void fma2(unsigned long long &d,
                                     unsigned long long a,
                                     unsigned long long b) {
    asm("fma.rn.f32x2 %0, %1, %2, %0;" : "+l"(d) : "l"(a), "l"(b));
}
__device__ __forceinline__ float2 unpack2(unsigned long long v) {
    float lo, hi;
    asm("mov.b64 {%0, %1}, %2;" : "=f"(lo), "=f"(hi) : "l"(v));
    return make_float2(lo, hi);
}

// ---------------- kernel A: relation table + edge counting (fused) ----------------
// blocks [0,64): g_rel[r][b*64+d] = bz[r*64+d] + sum_k z[b,k]*Wz[r*64+d,k]
// blocks [64, ...): histogram of dst into g_cnt (g_cnt is pre-zeroed)
__global__ void rel_count_kernel(const float* __restrict__ z,
                                 const float* __restrict__ Wz,
                                 const float* __restrict__ bz,
                                 const int* __restrict__ ei, int E) {
    __shared__ float zs[BD];
    __shared__ float wzt[64 * 65];   // transposed, padded
    int t = threadIdx.x;
    if (blockIdx.x < 64) {
        int r = blockIdx.x;
        zs[t] = z[t];
        for (int idx = t; idx < 64 * 64; idx += 256) {
            int dd = idx >> 6, k = idx & 63;
            wzt[k * 65 + dd] = Wz[(r * 64 + dd) * 64 + k];
        }
        __syncthreads();
        int b = t >> 6, d = t & 63;
        float acc = bz[r * 64 + d];
#pragma unroll
        for (int k = 0; k < 64; k++)
            acc = fmaf(zs[b * 64 + k], wzt[k * 65 + d], acc);
        g_rel[r * BD + t] = acc;
    } else {
        int base = (blockIdx.x - 64) * 1024 + t;
#pragma unroll
        for (int k = 0; k < 4; k++) {
            int e = base + k * 256;
            if (e < E) atomicAdd(&g_cnt[ei[e * 3 + 2]], 1);
        }
    }
}

// ---------------- 3-phase parallel exclusive scan over g_cnt[0..V) ----------------
__global__ void scan_part1(int V) {
    __shared__ int ws[8];
    int t = threadIdx.x;
    int i = blockIdx.x * 256 + t;
    int s = (i < V) ? g_cnt[i] : 0;
#pragma unroll
    for (int o = 16; o; o >>= 1) s += __shfl_xor_sync(0xFFFFFFFFu, s, o);
    if ((t & 31) == 0) ws[t >> 5] = s;
    __syncthreads();
    if (t == 0) {
        int tot = 0;
#pragma unroll
        for (int j = 0; j < 8; j++) tot += ws[j];
        g_bsum[blockIdx.x] = tot;
    }
}

__global__ void scan_part2(int NB, int V, int E) {
    __shared__ int sm[256];
    int t = threadIdx.x;
    int v = (t < NB) ? g_bsum[t] : 0;
    sm[t] = v;
    __syncthreads();
    for (int d = 1; d < 256; d <<= 1) {
        int u = (t >= d) ? sm[t - d] : 0;
        __syncthreads();
        sm[t] += u;
        __syncthreads();
    }
    if (t < NB) g_bbase[t] = sm[t] - v;   // exclusive
    if (t == 0) g_off[V] = E;
}

__global__ void scan_part3(int V) {
    __shared__ int ws[8];
    int t = threadIdx.x, lane = t & 31, w = t >> 5;
    int i = blockIdx.x * 256 + t;
    int c = (i < V) ? g_cnt[i] : 0;
    int inc = c;
#pragma unroll
    for (int o = 1; o < 32; o <<= 1) {
        int u = __shfl_up_sync(0xFFFFFFFFu, inc, o);
        if (lane >= o) inc += u;
    }
    if (lane == 31) ws[w] = inc;
    __syncthreads();
    if (w == 0 && lane < 8) {
        int ov = ws[lane];
        int x = ov;
#pragma unroll
        for (int o = 1; o < 8; o <<= 1) {
            int u = __shfl_up_sync(0x000000FFu, x, o);
            if (lane >= o) x += u;
        }
        ws[lane] = x - ov;  // exclusive warp base
    }
    __syncthreads();
    if (i < V) {
        int excl = inc - c + ws[w] + g_bbase[blockIdx.x];
        g_off[i] = excl;
        g_cur[i] = excl;
        g_cnt[i] = 0;       // reset for next graph replay
    }
}

__global__ void scatter_kernel(const int* __restrict__ ei, int E) {
    int e = blockIdx.x * blockDim.x + threadIdx.x;
    if (e >= E) return;
    int src = ei[e * 3 + 0];
    int et  = ei[e * 3 + 1];
    int dst = ei[e * 3 + 2];
    int p = atomicAdd(&g_cur[dst], 1);
    g_elist[p] = src | (et << 16);    // V<65536, R<65536
}

// ---------------- kernel C: aggregation (gather segment-sum) ----------------
// 64 threads per dst row (float4 per thread), 4 rows per 256-thread block.
// relation (64 KB) cached in dynamic smem; node gathers hit L2 (node set = 20 MB).
__global__ void agg_kernel(const float* __restrict__ x, int V) {
    extern __shared__ float rel_s[];  // 16384 floats = 64 KB
    for (int i = threadIdx.x; i < (Rc * BD) / 4; i += blockDim.x)
        ((float4*)rel_s)[i] = ((const float4*)g_rel)[i];
    __syncthreads();

    int ty = threadIdx.x >> 6;        // row slot 0..3
    int tx = threadIdx.x & 63;        // float4 lane: covers idx tx*4 = b*64+dbase
    int b = tx >> 4;
    int dbase = (tx << 2) & 63;
    const float* xb = x + (size_t)b * V * 64 + dbase;
    const float* relp = rel_s + tx * 4;

    for (int v = blockIdx.x * 4 + ty; v < V; v += gridDim.x * 4) {
        int s = g_off[v], e = g_off[v + 1];
        float4 acc = make_float4(0.f, 0.f, 0.f, 0.f);
#pragma unroll 8
        for (int i = s; i < e; i++) {
            int p = g_elist[i];
            int src = p & 0xFFFF;
            int et  = p >> 16;
            float4 nv = *(const float4*)(xb + src * 64);
            float4 rv = *(const float4*)(relp + et * BD);
            acc.x = fmaf(nv.x, rv.x, acc.x);
            acc.y = fmaf(nv.y, rv.y, acc.y);
            acc.z = fmaf(nv.z, rv.z, acc.z);
            acc.w = fmaf(nv.w, rv.w, acc.w);
        }
        *(float4*)(g_agg + (size_t)v * BD + tx * 4) = acc;
    }
}

// ---------------- kernel D: MLP (+beta*x, ReLU, LN, +x residual) ----------------
// 256 threads = one dst row (4 batches x 64 dims). Thread owns output column
// dq = tid&63 for batch b = tid>>6; both weight rows live in registers as
// packed f32x2 pairs; inner products use FFMA2 (2 MACs/instr).
__global__ void __launch_bounds__(256) mlp_kernel(
    const float* __restrict__ x,
    const float* __restrict__ W1, const float* __restrict__ b1,
    const float* __restrict__ W2, const float* __restrict__ b2,
    const float* __restrict__ beta,
    const float* __restrict__ lnw, const float* __restrict__ lnb,
    float* __restrict__ out, int V)
{
    __shared__ __align__(16) float hsA[BD];
    __shared__ __align__(16) float hsB[BD];
    __shared__ float red[16];
    int t = threadIdx.x;
    int b = t >> 6, dq = t & 63;
    int warp = t >> 5;

    // weights as packed f32x2 (adjacent k pairs), 64+64 u64 regs
    unsigned long long w1p[32], w2p[32];
    {
        const unsigned long long* W1q = (const unsigned long long*)(W1 + dq * 64);
        const unsigned long long* W2q = (const unsigned long long*)(W2 + dq * 64);
#pragma unroll
        for (int i = 0; i < 32; i++) { w1p[i] = W1q[i]; w2p[i] = W2q[i]; }
    }
    float b1r = b1[dq], b2r = b2[dq];
    float betar = beta[dq], lnwr = lnw[dq], lnbr = lnb[dq];

    const float* xb = x + (size_t)b * V * 64;
    float*       ob = out + (size_t)b * V * 64;

    int v0 = blockIdx.x;
    float xvn = 0.f, agn = 0.f;
    if (v0 < V) {
        xvn = xb[v0 * 64 + dq];
        agn = g_agg[(size_t)v0 * BD + t];
    }

    for (int v = v0; v < V; v += gridDim.x) {
        float xv = xvn;
        float h0 = agn + betar * xv;
        // prefetch next row (hidden behind the barriers + GEMMs below)
        int vn = v + gridDim.x;
        if (vn < V) {
            xvn = xb[vn * 64 + dq];
            agn = g_agg[(size_t)vn * BD + t];
        }
        hsA[t] = h0;
        __syncthreads();

        // h1 = relu(h0 @ W1^T + b1)   — FFMA2, two independent chains
        unsigned long long acc0 = 0ull, acc1 = 0ull;
        {
            const ulonglong2* hp = (const ulonglong2*)(hsA + (b << 6));
#pragma unroll
            for (int i = 0; i < 16; i++) {
                ulonglong2 h2 = hp[i];
                fma2(acc0, h2.x, w1p[2 * i]);
                fma2(acc1, h2.y, w1p[2 * i + 1]);
            }
        }
        float2 s0 = unpack2(acc0), s1 = unpack2(acc1);
        float a1 = fmaxf(s0.x + s0.y + s1.x + s1.y + b1r, 0.f);
        hsB[t] = a1;
        __syncthreads();

        // h2 = h1 @ W2^T + b2
        acc0 = 0ull; acc1 = 0ull;
        {
            const ulonglong2* hp2 = (const ulonglong2*)(hsB + (b << 6));
#pragma unroll
            for (int i = 0; i < 16; i++) {
                ulonglong2 h2 = hp2[i];
                fma2(acc0, h2.x, w2p[2 * i]);
                fma2(acc1, h2.y, w2p[2 * i + 1]);
            }
        }
        s0 = unpack2(acc0); s1 = unpack2(acc1);
        float a2 = s0.x + s0.y + s1.x + s1.y + b2r;

        // LayerNorm over the 64 dims of this (b, v) row (2 warps per row)
        float s = a2, sq = a2 * a2;
#pragma unroll
        for (int o = 16; o; o >>= 1) {
            s  += __shfl_xor_sync(0xFFFFFFFFu, s,  o);
            sq += __shfl_xor_sync(0xFFFFFFFFu, sq, o);
        }
        if ((t & 31) == 0) { red[warp * 2] = s; red[warp * 2 + 1] = sq; }
        __syncthreads();
        float st  = red[4 * b + 0] + red[4 * b + 2];
        float sqt = red[4 * b + 1] + red[4 * b + 3];
        float mu  = st * (1.f / 64.f);
        float var = sqt * (1.f / 64.f) - mu * mu;
        float o = (a2 - mu) * rsqrtf(var + LN_EPS) * lnwr + lnbr + xv;
        ob[v * 64 + dq] = o;
        // next-iter hsA write is safe: all hsA/hsB/red reads of this iteration
        // precede barriers that every thread has passed before the next write.
    }
}

// ---------------- launch ----------------
extern "C" void kernel_launch(void* const* d_in, const int* in_sizes, int n_in,
                              void* d_out, int out_size) {
    const float* x    = (const float*)d_in[0];
    const float* z    = (const float*)d_in[1];
    const int*   ei   = (const int*)  d_in[2];
    // d_in[3] = r_index (unused by reference)
    const float* Wz   = (const float*)d_in[4];
    const float* bz   = (const float*)d_in[5];
    const float* W1   = (const float*)d_in[6];
    const float* b1   = (const float*)d_in[7];
    const float* W2   = (const float*)d_in[8];
    const float* b2   = (const float*)d_in[9];
    const float* beta = (const float*)d_in[10];
    const float* lnw  = (const float*)d_in[11];
    const float* lnb  = (const float*)d_in[12];
    float* out = (float*)d_out;

    int E = in_sizes[2] / 3;
    int V = in_sizes[0] / (Bc * Dc);
    int NB = (V + 255) / 256;   // scan blocks (79 for V=20000)

    rel_count_kernel<<<64 + (E + 1023) / 1024, 256>>>(z, Wz, bz, ei, E);
    scan_part1<<<NB, 256>>>(V);
    scan_part2<<<1, 256>>>(NB, V, E);
    scan_part3<<<NB, 256>>>(V);
    scatter_kernel<<<(E + 255) / 256, 256>>>(ei, E);

    cudaFuncSetAttribute((const void*)agg_kernel,
                         cudaFuncAttributeMaxDynamicSharedMemorySize, 65536);
    agg_kernel<<<444, 256, 65536>>>(x, V);

    mlp_kernel<<<148, 256>>>(x, W1, b1, W2, b2, beta, lnw, lnb, out, V);
}

// round 7
// speedup vs baseline: 1.7079x; 1.1762x over previous
#include <cuda_runtime.h>
#include <cuda_bf16.h>

// Shapes (fixed for this problem): B=4, V=20000, D=64, R=64, E=640000
#define Bc   4
#define Dc   64
#define Rc   64
#define BD   256          // B*D
#define VMAX 20000
#define EMAX 640000
#define LN_EPS 1e-5f

// ---------------- device scratch (no allocations allowed) ----------------
__device__ float g_rel[Rc * BD];        // relation[r][b*64+d]   (64 KB)
__device__ int   g_cnt[VMAX + 1];       // zero-init; re-zeroed inside scan each run
__device__ int   g_off[VMAX + 1];
__device__ int   g_cur[VMAX];
__device__ int   g_elist[EMAX];         // packed: src | (etype<<16)
__device__ float g_agg[(size_t)VMAX * BD];  // 20 MB
__device__ int   g_tpart[256];          // tile aggregate + 1   (0 = not ready)
__device__ int   g_tincl[256];          // tile inclusive + 1   (0 = not ready)
                                        // both reset by scatter_kernel for next replay

// ---------------- packed f32x2 helpers (Blackwell FFMA2) ----------------
__device__ __forceinline__ void fma2(unsigned long long &d,
                                     unsigned long long a,
                                     unsigned long long b) {
    asm("fma.rn.f32x2 %0, %1, %2, %0;" : "+l"(d) : "l"(a), "l"(b));
}
__device__ __forceinline__ float2 unpack2(unsigned long long v) {
    float lo, hi;
    asm("mov.b64 {%0, %1}, %2;" : "=f"(lo), "=f"(hi) : "l"(v));
    return make_float2(lo, hi);
}
__device__ __forceinline__ int ldacq(const int* p) {
    int v;
    asm volatile("ld.acquire.gpu.s32 %0, [%1];" : "=r"(v) : "l"(p));
    return v;
}
__device__ __forceinline__ void strel(int* p, int v) {
    asm volatile("st.release.gpu.s32 [%0], %1;" :: "l"(p), "r"(v) : "memory");
}

// ---------------- kernel 1: relation table + edge counting (fused) ----------------
__global__ void rel_count_kernel(const float* __restrict__ z,
                                 const float* __restrict__ Wz,
                                 const float* __restrict__ bz,
                                 const int* __restrict__ ei, int E) {
    __shared__ float zs[BD];
    __shared__ float wzt[64 * 65];
    int t = threadIdx.x;
    if (blockIdx.x < 64) {
        int r = blockIdx.x;
        zs[t] = z[t];
        for (int idx = t; idx < 64 * 64; idx += 256) {
            int dd = idx >> 6, k = idx & 63;
            wzt[k * 65 + dd] = Wz[(r * 64 + dd) * 64 + k];
        }
        __syncthreads();
        int b = t >> 6, d = t & 63;
        float acc = bz[r * 64 + d];
#pragma unroll
        for (int k = 0; k < 64; k++)
            acc = fmaf(zs[b * 64 + k], wzt[k * 65 + d], acc);
        g_rel[r * BD + t] = acc;
    } else {
        int base = (blockIdx.x - 64) * 1024 + t;
#pragma unroll
        for (int k = 0; k < 4; k++) {
            int e = base + k * 256;
            if (e < E) atomicAdd(&g_cnt[ei[e * 3 + 2]], 1);
        }
    }
}

// ---------------- kernel 2: single-pass exclusive scan (decoupled lookback) ----------------
// NB blocks of 256 (NB=79 <= 148, all resident -> spin-safe).
__global__ void scan_lookback(int V, int E, int NB) {
    __shared__ int ws[8];
    __shared__ int s_base;
    int t = threadIdx.x, lane = t & 31, w = t >> 5, bid = blockIdx.x;
    int i = bid * 256 + t;
    int c = (i < V) ? g_cnt[i] : 0;

    // warp inclusive scan
    int inc = c;
#pragma unroll
    for (int o = 1; o < 32; o <<= 1) {
        int u = __shfl_up_sync(0xFFFFFFFFu, inc, o);
        if (lane >= o) inc += u;
    }
    if (lane == 31) ws[w] = inc;
    __syncthreads();

    if (w == 0) {
        // scan the 8 warp totals (lanes 0..7 meaningful)
        int v8 = (lane < 8) ? ws[lane] : 0;
        int sc = v8;
#pragma unroll
        for (int o = 1; o < 8; o <<= 1) {
            int u = __shfl_up_sync(0xFFFFFFFFu, sc, o);
            if (lane >= o) sc += u;
        }
        int total = __shfl_sync(0xFFFFFFFFu, sc, 7);
        if (lane < 8) ws[lane] = sc - v8;              // exclusive warp bases
        if (lane == 0) strel(&g_tpart[bid], total + 1); // publish partial

        // windowed lookback
        int base = 0;
        int j = bid - 1;
        while (j >= 0) {
            int idx = j - lane;
            int iv = 0, pv = 0;
            if (idx >= 0) {
                iv = ldacq(&g_tincl[idx]);
                pv = ldacq(&g_tpart[idx]);
            }
            unsigned mi = __ballot_sync(0xFFFFFFFFu, iv != 0);
            unsigned mp = __ballot_sync(0xFFFFFFFFu, pv != 0);
            if (mi) {
                int li = __ffs(mi) - 1;                 // nearest inclusive-ready tile
                unsigned need = (li == 0) ? 0u : ((1u << li) - 1u);
                if ((mp & need) == need) {
                    int contrib = 0;
                    if (lane < li) contrib = pv - 1;
                    else if (lane == li) contrib = iv - 1;
#pragma unroll
                    for (int o = 16; o; o >>= 1)
                        contrib += __shfl_xor_sync(0xFFFFFFFFu, contrib, o);
                    base += contrib;
                    break;
                }
            } else {
                int wcount = (j + 1 < 32) ? (j + 1) : 32;
                unsigned needall = (wcount == 32) ? 0xFFFFFFFFu : ((1u << wcount) - 1u);
                if ((mp & needall) == needall) {
                    int contrib = (idx >= 0) ? (pv - 1) : 0;
#pragma unroll
                    for (int o = 16; o; o >>= 1)
                        contrib += __shfl_xor_sync(0xFFFFFFFFu, contrib, o);
                    base += contrib;
                    j -= wcount;
                }
            }
        }
        if (lane == 0) {
            s_base = base;
            strel(&g_tincl[bid], base + total + 1);     // publish inclusive
        }
    }
    __syncthreads();

    int base = s_base;
    if (i < V) {
        int excl = base + ws[w] + inc - c;
        g_off[i] = excl;
        g_cur[i] = excl;
        g_cnt[i] = 0;            // reset for next replay
    }
    if (bid == 0 && t == 0) g_off[V] = E;
}

// ---------------- kernel 3: scatter (+ reset lookback flags for next replay) ----------------
__global__ void scatter_kernel(const int* __restrict__ ei, int E) {
    int e = blockIdx.x * blockDim.x + threadIdx.x;
    if (e < 256) { g_tpart[e] = 0; g_tincl[e] = 0; }
    if (e >= E) return;
    int src = ei[e * 3 + 0];
    int et  = ei[e * 3 + 1];
    int dst = ei[e * 3 + 2];
    int p = atomicAdd(&g_cur[dst], 1);
    g_elist[p] = src | (et << 16);
}

// ---------------- kernel 4: aggregation (gather segment-sum) ----------------
// 512 threads = 8 dst rows x 64 lanes (float4/lane). 3 blocks/SM -> 48 warps/SM.
__global__ void __launch_bounds__(512) agg_kernel(const float* __restrict__ x, int V) {
    extern __shared__ float rel_s[];  // 64 KB
    for (int i = threadIdx.x; i < (Rc * BD) / 4; i += blockDim.x)
        ((float4*)rel_s)[i] = ((const float4*)g_rel)[i];
    __syncthreads();

    int ty = threadIdx.x >> 6;        // row slot 0..7
    int tx = threadIdx.x & 63;
    int b = tx >> 4;
    int dbase = (tx << 2) & 63;
    const float* xb = x + (size_t)b * V * 64 + dbase;
    const float* relp = rel_s + tx * 4;

    for (int v = blockIdx.x * 8 + ty; v < V; v += gridDim.x * 8) {
        int s = g_off[v], e = g_off[v + 1];
        float4 acc = make_float4(0.f, 0.f, 0.f, 0.f);
#pragma unroll 8
        for (int i = s; i < e; i++) {
            int p = g_elist[i];
            int src = p & 0xFFFF;
            int et  = p >> 16;
            float4 nv = *(const float4*)(xb + src * 64);
            float4 rv = *(const float4*)(relp + et * BD);
            acc.x = fmaf(nv.x, rv.x, acc.x);
            acc.y = fmaf(nv.y, rv.y, acc.y);
            acc.z = fmaf(nv.z, rv.z, acc.z);
            acc.w = fmaf(nv.w, rv.w, acc.w);
        }
        *(float4*)(g_agg + (size_t)v * BD + tx * 4) = acc;
    }
}

// ---------------- kernel 5: MLP, 2 rows per barrier cycle ----------------
__global__ void __launch_bounds__(256) mlp_kernel(
    const float* __restrict__ x,
    const float* __restrict__ W1, const float* __restrict__ b1,
    const float* __restrict__ W2, const float* __restrict__ b2,
    const float* __restrict__ beta,
    const float* __restrict__ lnw, const float* __restrict__ lnb,
    float* __restrict__ out, int V)
{
    __shared__ __align__(16) float hsA[2][BD];
    __shared__ __align__(16) float hsB[2][BD];
    __shared__ float red[2][16];
    int t = threadIdx.x;
    int b = t >> 6, dq = t & 63;
    int warp = t >> 5, lane = t & 31;

    unsigned long long w1p[32], w2p[32];
    {
        const unsigned long long* W1q = (const unsigned long long*)(W1 + dq * 64);
        const unsigned long long* W2q = (const unsigned long long*)(W2 + dq * 64);
#pragma unroll
        for (int i = 0; i < 32; i++) { w1p[i] = W1q[i]; w2p[i] = W2q[i]; }
    }
    float b1r = b1[dq], b2r = b2[dq];
    float betar = beta[dq], lnwr = lnw[dq], lnbr = lnb[dq];

    const float* xb = x + (size_t)b * V * 64;
    float*       ob = out + (size_t)b * V * 64;

    int stride = gridDim.x * 2;
    int v0 = blockIdx.x * 2;
    float xv0 = 0.f, xv1 = 0.f, ag0 = 0.f, ag1 = 0.f;
    if (v0 < V)     { xv0 = xb[v0 * 64 + dq];       ag0 = g_agg[(size_t)v0 * BD + t]; }
    if (v0 + 1 < V) { xv1 = xb[(v0 + 1) * 64 + dq]; ag1 = g_agg[(size_t)(v0 + 1) * BD + t]; }

    for (int v = v0; v < V; v += stride) {
        bool has1 = (v + 1 < V);
        float xva = xv0, xvb = xv1;
        float h0a = ag0 + betar * xva;
        float h0b = ag1 + betar * xvb;
        int vn = v + stride;
        if (vn < V)     { xv0 = xb[vn * 64 + dq];       ag0 = g_agg[(size_t)vn * BD + t]; }
        if (vn + 1 < V) { xv1 = xb[(vn + 1) * 64 + dq]; ag1 = g_agg[(size_t)(vn + 1) * BD + t]; }

        hsA[0][t] = h0a;
        hsA[1][t] = h0b;
        __syncthreads();

        // GEMV1 for both rows (FFMA2, 4 independent chains)
        unsigned long long a00 = 0ull, a01 = 0ull, a10 = 0ull, a11 = 0ull;
        {
            const ulonglong2* hp0 = (const ulonglong2*)(hsA[0] + (b << 6));
            const ulonglong2* hp1 = (const ulonglong2*)(hsA[1] + (b << 6));
#pragma unroll
            for (int i = 0; i < 16; i++) {
                ulonglong2 q0 = hp0[i], q1 = hp1[i];
                fma2(a00, q0.x, w1p[2 * i]);
                fma2(a01, q0.y, w1p[2 * i + 1]);
                fma2(a10, q1.x, w1p[2 * i]);
                fma2(a11, q1.y, w1p[2 * i + 1]);
            }
        }
        float2 s0 = unpack2(a00), s1 = unpack2(a01);
        float r1a = fmaxf(s0.x + s0.y + s1.x + s1.y + b1r, 0.f);
        s0 = unpack2(a10); s1 = unpack2(a11);
        float r1b = fmaxf(s0.x + s0.y + s1.x + s1.y + b1r, 0.f);
        hsB[0][t] = r1a;
        hsB[1][t] = r1b;
        __syncthreads();

        // GEMV2 for both rows
        a00 = 0ull; a01 = 0ull; a10 = 0ull; a11 = 0ull;
        {
            const ulonglong2* hp0 = (const ulonglong2*)(hsB[0] + (b << 6));
            const ulonglong2* hp1 = (const ulonglong2*)(hsB[1] + (b << 6));
#pragma unroll
            for (int i = 0; i < 16; i++) {
                ulonglong2 q0 = hp0[i], q1 = hp1[i];
                fma2(a00, q0.x, w2p[2 * i]);
                fma2(a01, q0.y, w2p[2 * i + 1]);
                fma2(a10, q1.x, w2p[2 * i]);
                fma2(a11, q1.y, w2p[2 * i + 1]);
            }
        }
        s0 = unpack2(a00); s1 = unpack2(a01);
        float a2a = s0.x + s0.y + s1.x + s1.y + b2r;
        s0 = unpack2(a10); s1 = unpack2(a11);
        float a2b = s0.x + s0.y + s1.x + s1.y + b2r;

        // LayerNorm reductions for both rows (interleaved shuffle chains)
        float sa = a2a, qa = a2a * a2a, sb = a2b, qb = a2b * a2b;
#pragma unroll
        for (int o = 16; o; o >>= 1) {
            sa += __shfl_xor_sync(0xFFFFFFFFu, sa, o);
            qa += __shfl_xor_sync(0xFFFFFFFFu, qa, o);
            sb += __shfl_xor_sync(0xFFFFFFFFu, sb, o);
            qb += __shfl_xor_sync(0xFFFFFFFFu, qb, o);
        }
        if (lane == 0) {
            red[0][warp * 2] = sa; red[0][warp * 2 + 1] = qa;
            red[1][warp * 2] = sb; red[1][warp * 2 + 1] = qb;
        }
        __syncthreads();

        {
            float st  = red[0][4 * b + 0] + red[0][4 * b + 2];
            float sqt = red[0][4 * b + 1] + red[0][4 * b + 3];
            float mu  = st * (1.f / 64.f);
            float var = sqt * (1.f / 64.f) - mu * mu;
            ob[v * 64 + dq] = (a2a - mu) * rsqrtf(var + LN_EPS) * lnwr + lnbr + xva;
        }
        if (has1) {
            float st  = red[1][4 * b + 0] + red[1][4 * b + 2];
            float sqt = red[1][4 * b + 1] + red[1][4 * b + 3];
            float mu  = st * (1.f / 64.f);
            float var = sqt * (1.f / 64.f) - mu * mu;
            ob[(v + 1) * 64 + dq] = (a2b - mu) * rsqrtf(var + LN_EPS) * lnwr + lnbr + xvb;
        }
        // next-iter hsA writes are safe: every thread passed the red barrier,
        // which postdates all hsA/hsB reads of this iteration.
    }
}

// ---------------- launch ----------------
extern "C" void kernel_launch(void* const* d_in, const int* in_sizes, int n_in,
                              void* d_out, int out_size) {
    const float* x    = (const float*)d_in[0];
    const float* z    = (const float*)d_in[1];
    const int*   ei   = (const int*)  d_in[2];
    // d_in[3] = r_index (unused by reference)
    const float* Wz   = (const float*)d_in[4];
    const float* bz   = (const float*)d_in[5];
    const float* W1   = (const float*)d_in[6];
    const float* b1   = (const float*)d_in[7];
    const float* W2   = (const float*)d_in[8];
    const float* b2   = (const float*)d_in[9];
    const float* beta = (const float*)d_in[10];
    const float* lnw  = (const float*)d_in[11];
    const float* lnb  = (const float*)d_in[12];
    float* out = (float*)d_out;

    int E = in_sizes[2] / 3;
    int V = in_sizes[0] / (Bc * Dc);
    int NB = (V + 255) / 256;   // 79 for V=20000 (must be <= 148 for resident spin)

    rel_count_kernel<<<64 + (E + 1023) / 1024, 256>>>(z, Wz, bz, ei, E);
    scan_lookback<<<NB, 256>>>(V, E, NB);
    scatter_kernel<<<(E + 255) / 256, 256>>>(ei, E);

    cudaFuncSetAttribute((const void*)agg_kernel,
                         cudaFuncAttributeMaxDynamicSharedMemorySize, 65536);
    agg_kernel<<<444, 512, 65536>>>(x, V);

    mlp_kernel<<<148, 256>>>(x, W1, b1, W2, b2, beta, lnw, lnb, out, V);
}

// round 8
// speedup vs baseline: 1.8533x; 1.0852x over previous
#include <cuda_runtime.h>
#include <cuda_fp16.h>
#include <cuda_bf16.h>

// Shapes (fixed for this problem): B=4, V=20000, D=64, R=64, E=640000
#define Bc   4
#define Dc   64
#define Rc   64
#define BD   256          // B*D
#define VMAX 20000
#define EMAX 640000
#define LN_EPS 1e-5f

// ---------------- device scratch (no allocations allowed) ----------------
__device__ float  g_rel[Rc * BD];        // relation[r][b*64+d]   (64 KB)
__device__ int    g_cnt[VMAX + 1];       // zero-init; re-zeroed inside scan each run
__device__ int    g_off[VMAX + 1];
__device__ int    g_cur[VMAX];
__device__ __align__(16) int g_elist[EMAX];   // packed: src | (etype<<16)
__device__ float  g_agg[(size_t)VMAX * BD];   // 20 MB
__device__ __half g_xh[(size_t)Bc * VMAX * Dc]; // fp16 copy of x (10 MB)
__device__ int    g_tpart[256];          // tile aggregate + 1   (0 = not ready)
__device__ int    g_tincl[256];          // tile inclusive + 1   (0 = not ready)

// ---------------- packed f32x2 helpers (Blackwell FFMA2) ----------------
__device__ __forceinline__ void fma2(unsigned long long &d,
                                     unsigned long long a,
                                     unsigned long long b) {
    asm("fma.rn.f32x2 %0, %1, %2, %0;" : "+l"(d) : "l"(a), "l"(b));
}
__device__ __forceinline__ float2 unpack2(unsigned long long v) {
    float lo, hi;
    asm("mov.b64 {%0, %1}, %2;" : "=f"(lo), "=f"(hi) : "l"(v));
    return make_float2(lo, hi);
}
__device__ __forceinline__ int ldacq(const int* p) {
    int v;
    asm volatile("ld.acquire.gpu.s32 %0, [%1];" : "=r"(v) : "l"(p));
    return v;
}
__device__ __forceinline__ void strel(int* p, int v) {
    asm volatile("st.release.gpu.s32 [%0], %1;" :: "l"(p), "r"(v) : "memory");
}

// ---------------- kernel 1: relation table + edge counting + x->fp16 (fused) ----
// blocks [0,64): relation GEMM; [64,64+NC): dst histogram; [64+NC, ...): x->half
__global__ void rel_count_kernel(const float* __restrict__ z,
                                 const float* __restrict__ Wz,
                                 const float* __restrict__ bz,
                                 const int* __restrict__ ei, int E,
                                 const float* __restrict__ x, int N4, int NC) {
    __shared__ float zs[BD];
    __shared__ float wzt[64 * 65];
    int t = threadIdx.x;
    if (blockIdx.x < 64) {
        int r = blockIdx.x;
        zs[t] = z[t];
        for (int idx = t; idx < 64 * 64; idx += 256) {
            int dd = idx >> 6, k = idx & 63;
            wzt[k * 65 + dd] = Wz[(r * 64 + dd) * 64 + k];
        }
        __syncthreads();
        int b = t >> 6, d = t & 63;
        float acc = bz[r * 64 + d];
#pragma unroll
        for (int k = 0; k < 64; k++)
            acc = fmaf(zs[b * 64 + k], wzt[k * 65 + d], acc);
        g_rel[r * BD + t] = acc;
    } else if (blockIdx.x < 64 + NC) {
        int base = (blockIdx.x - 64) * 1024 + t;
#pragma unroll
        for (int k = 0; k < 4; k++) {
            int e = base + k * 256;
            if (e < E) atomicAdd(&g_cnt[ei[e * 3 + 2]], 1);
        }
    } else {
        // convert x (fp32) -> g_xh (fp16), float4 granularity, 8 per thread
        int base = (blockIdx.x - 64 - NC) * 2048 + t;
        uint2* dst = (uint2*)g_xh;
        const float4* src = (const float4*)x;
#pragma unroll
        for (int k = 0; k < 8; k++) {
            int idx = base + k * 256;
            if (idx < N4) {
                float4 f = src[idx];
                __half2 h01 = __floats2half2_rn(f.x, f.y);
                __half2 h23 = __floats2half2_rn(f.z, f.w);
                uint2 o;
                o.x = *(unsigned*)&h01;
                o.y = *(unsigned*)&h23;
                dst[idx] = o;
            }
        }
    }
}

// ---------------- kernel 2: single-pass exclusive scan (decoupled lookback) ----------------
__global__ void scan_lookback(int V, int E, int NB) {
    __shared__ int ws[8];
    __shared__ int s_base;
    int t = threadIdx.x, lane = t & 31, w = t >> 5, bid = blockIdx.x;
    int i = bid * 256 + t;
    int c = (i < V) ? g_cnt[i] : 0;

    int inc = c;
#pragma unroll
    for (int o = 1; o < 32; o <<= 1) {
        int u = __shfl_up_sync(0xFFFFFFFFu, inc, o);
        if (lane >= o) inc += u;
    }
    if (lane == 31) ws[w] = inc;
    __syncthreads();

    if (w == 0) {
        int v8 = (lane < 8) ? ws[lane] : 0;
        int sc = v8;
#pragma unroll
        for (int o = 1; o < 8; o <<= 1) {
            int u = __shfl_up_sync(0xFFFFFFFFu, sc, o);
            if (lane >= o) sc += u;
        }
        int total = __shfl_sync(0xFFFFFFFFu, sc, 7);
        if (lane < 8) ws[lane] = sc - v8;
        if (lane == 0) strel(&g_tpart[bid], total + 1);

        int base = 0;
        int j = bid - 1;
        while (j >= 0) {
            int idx = j - lane;
            int iv = 0, pv = 0;
            if (idx >= 0) {
                iv = ldacq(&g_tincl[idx]);
                pv = ldacq(&g_tpart[idx]);
            }
            unsigned mi = __ballot_sync(0xFFFFFFFFu, iv != 0);
            unsigned mp = __ballot_sync(0xFFFFFFFFu, pv != 0);
            if (mi) {
                int li = __ffs(mi) - 1;
                unsigned need = (li == 0) ? 0u : ((1u << li) - 1u);
                if ((mp & need) == need) {
                    int contrib = 0;
                    if (lane < li) contrib = pv - 1;
                    else if (lane == li) contrib = iv - 1;
#pragma unroll
                    for (int o = 16; o; o >>= 1)
                        contrib += __shfl_xor_sync(0xFFFFFFFFu, contrib, o);
                    base += contrib;
                    break;
                }
            } else {
                int wcount = (j + 1 < 32) ? (j + 1) : 32;
                unsigned needall = (wcount == 32) ? 0xFFFFFFFFu : ((1u << wcount) - 1u);
                if ((mp & needall) == needall) {
                    int contrib = (idx >= 0) ? (pv - 1) : 0;
#pragma unroll
                    for (int o = 16; o; o >>= 1)
                        contrib += __shfl_xor_sync(0xFFFFFFFFu, contrib, o);
                    base += contrib;
                    j -= wcount;
                }
            }
        }
        if (lane == 0) {
            s_base = base;
            strel(&g_tincl[bid], base + total + 1);
        }
    }
    __syncthreads();

    int base = s_base;
    if (i < V) {
        int excl = base + ws[w] + inc - c;
        g_off[i] = excl;
        g_cur[i] = excl;
        g_cnt[i] = 0;
    }
    if (bid == 0 && t == 0) g_off[V] = E;
}

// ---------------- kernel 3: scatter (+ reset lookback flags for next replay) ----------------
__global__ void scatter_kernel(const int* __restrict__ ei, int E) {
    int e = blockIdx.x * blockDim.x + threadIdx.x;
    if (e < 256) { g_tpart[e] = 0; g_tincl[e] = 0; }
    if (e >= E) return;
    int src = ei[e * 3 + 0];
    int et  = ei[e * 3 + 1];
    int dst = ei[e * 3 + 2];
    int p = atomicAdd(&g_cur[dst], 1);
    g_elist[p] = src | (et << 16);
}

// ---------------- kernel 4: aggregation (fp16 gather segment-sum) ----------------
// 1024 threads = 16 dst rows x 64 lanes. 2 blocks/SM -> 64 warps/SM.
// Node gather in fp16 (4 L1 lines/edge), rel in fp32 smem (precision).
__global__ void __launch_bounds__(1024, 2) agg_kernel(int V) {
    extern __shared__ float rel_s[];  // 64 KB
    for (int i = threadIdx.x; i < (Rc * BD) / 4; i += blockDim.x)
        ((float4*)rel_s)[i] = ((const float4*)g_rel)[i];
    __syncthreads();

    int ty = threadIdx.x >> 6;        // row slot 0..15
    int tx = threadIdx.x & 63;
    int b = tx >> 4;
    int dbase = (tx << 2) & 63;
    const __half* xhp = g_xh + (size_t)b * V * 64 + dbase;
    const float* relp = rel_s + tx * 4;

    for (int v = blockIdx.x * 16 + ty; v < V; v += gridDim.x * 16) {
        int s = g_off[v], e = g_off[v + 1];
        float4 acc = make_float4(0.f, 0.f, 0.f, 0.f);
        int i = s;
        // ragged head to 4-alignment
        for (; i < e && (i & 3); i++) {
            int p = g_elist[i];
            uint2 nh = *(const uint2*)(xhp + (size_t)(p & 0xFFFF) * 64);
            const float4 rv = *(const float4*)(relp + (p >> 16) * BD);
            float2 n01 = __half22float2(*(const __half2*)&nh.x);
            float2 n23 = __half22float2(*(const __half2*)&nh.y);
            acc.x = fmaf(n01.x, rv.x, acc.x);
            acc.y = fmaf(n01.y, rv.y, acc.y);
            acc.z = fmaf(n23.x, rv.z, acc.z);
            acc.w = fmaf(n23.y, rv.w, acc.w);
        }
        // 4-edge batches (int4 broadcast load of elist)
        for (; i + 4 <= e; i += 4) {
            int4 p4 = *(const int4*)(g_elist + i);
#pragma unroll
            for (int k = 0; k < 4; k++) {
                int p = (k == 0) ? p4.x : (k == 1) ? p4.y : (k == 2) ? p4.z : p4.w;
                uint2 nh = *(const uint2*)(xhp + (size_t)(p & 0xFFFF) * 64);
                const float4 rv = *(const float4*)(relp + (p >> 16) * BD);
                float2 n01 = __half22float2(*(const __half2*)&nh.x);
                float2 n23 = __half22float2(*(const __half2*)&nh.y);
                acc.x = fmaf(n01.x, rv.x, acc.x);
                acc.y = fmaf(n01.y, rv.y, acc.y);
                acc.z = fmaf(n23.x, rv.z, acc.z);
                acc.w = fmaf(n23.y, rv.w, acc.w);
            }
        }
        // tail
        for (; i < e; i++) {
            int p = g_elist[i];
            uint2 nh = *(const uint2*)(xhp + (size_t)(p & 0xFFFF) * 64);
            const float4 rv = *(const float4*)(relp + (p >> 16) * BD);
            float2 n01 = __half22float2(*(const __half2*)&nh.x);
            float2 n23 = __half22float2(*(const __half2*)&nh.y);
            acc.x = fmaf(n01.x, rv.x, acc.x);
            acc.y = fmaf(n01.y, rv.y, acc.y);
            acc.z = fmaf(n23.x, rv.z, acc.z);
            acc.w = fmaf(n23.y, rv.w, acc.w);
        }
        *(float4*)(g_agg + (size_t)v * BD + tx * 4) = acc;
    }
}

// ---------------- kernel 5: MLP, 4 rows per barrier cycle ----------------
__global__ void __launch_bounds__(256) mlp_kernel(
    const float* __restrict__ x,
    const float* __restrict__ W1, const float* __restrict__ b1,
    const float* __restrict__ W2, const float* __restrict__ b2,
    const float* __restrict__ beta,
    const float* __restrict__ lnw, const float* __restrict__ lnb,
    float* __restrict__ out, int V)
{
    __shared__ __align__(16) float hsA[4][BD];
    __shared__ __align__(16) float hsB[4][BD];
    __shared__ float red[4][16];
    int t = threadIdx.x;
    int b = t >> 6, dq = t & 63;
    int warp = t >> 5, lane = t & 31;

    unsigned long long w1p[32], w2p[32];
    {
        const unsigned long long* W1q = (const unsigned long long*)(W1 + dq * 64);
        const unsigned long long* W2q = (const unsigned long long*)(W2 + dq * 64);
#pragma unroll
        for (int i = 0; i < 32; i++) { w1p[i] = W1q[i]; w2p[i] = W2q[i]; }
    }
    float b1r = b1[dq], b2r = b2[dq];
    float betar = beta[dq], lnwr = lnw[dq], lnbr = lnb[dq];

    const float* xb = x + (size_t)b * V * 64;
    float*       ob = out + (size_t)b * V * 64;

    int stride = gridDim.x * 4;
    int v0 = blockIdx.x * 4;
    float xvn[4], agn[4];
#pragma unroll
    for (int j = 0; j < 4; j++) {
        int vv = v0 + j;
        if (vv < V) { xvn[j] = xb[vv * 64 + dq]; agn[j] = g_agg[(size_t)vv * BD + t]; }
        else        { xvn[j] = 0.f;              agn[j] = 0.f; }
    }

    for (int v = v0; v < V; v += stride) {
        float xva[4];
#pragma unroll
        for (int j = 0; j < 4; j++) {
            xva[j] = xvn[j];
            hsA[j][t] = agn[j] + betar * xva[j];
        }
        int vn = v + stride;
#pragma unroll
        for (int j = 0; j < 4; j++) {
            int vv = vn + j;
            if (vv < V) { xvn[j] = xb[vv * 64 + dq]; agn[j] = g_agg[(size_t)vv * BD + t]; }
        }
        __syncthreads();

        // GEMV1 (FFMA2, 8 independent chains, smem broadcast reads)
        unsigned long long a[8];
#pragma unroll
        for (int j = 0; j < 8; j++) a[j] = 0ull;
        {
            const ulonglong2* h0 = (const ulonglong2*)(hsA[0] + (b << 6));
            const ulonglong2* h1 = (const ulonglong2*)(hsA[1] + (b << 6));
            const ulonglong2* h2 = (const ulonglong2*)(hsA[2] + (b << 6));
            const ulonglong2* h3 = (const ulonglong2*)(hsA[3] + (b << 6));
#pragma unroll
            for (int i = 0; i < 16; i++) {
                ulonglong2 q0 = h0[i], q1 = h1[i], q2 = h2[i], q3 = h3[i];
                fma2(a[0], q0.x, w1p[2 * i]); fma2(a[1], q0.y, w1p[2 * i + 1]);
                fma2(a[2], q1.x, w1p[2 * i]); fma2(a[3], q1.y, w1p[2 * i + 1]);
                fma2(a[4], q2.x, w1p[2 * i]); fma2(a[5], q2.y, w1p[2 * i + 1]);
                fma2(a[6], q3.x, w1p[2 * i]); fma2(a[7], q3.y, w1p[2 * i + 1]);
            }
        }
#pragma unroll
        for (int j = 0; j < 4; j++) {
            float2 s0 = unpack2(a[2 * j]), s1 = unpack2(a[2 * j + 1]);
            hsB[j][t] = fmaxf(s0.x + s0.y + s1.x + s1.y + b1r, 0.f);
        }
        __syncthreads();

        // GEMV2
#pragma unroll
        for (int j = 0; j < 8; j++) a[j] = 0ull;
        {
            const ulonglong2* h0 = (const ulonglong2*)(hsB[0] + (b << 6));
            const ulonglong2* h1 = (const ulonglong2*)(hsB[1] + (b << 6));
            const ulonglong2* h2 = (const ulonglong2*)(hsB[2] + (b << 6));
            const ulonglong2* h3 = (const ulonglong2*)(hsB[3] + (b << 6));
#pragma unroll
            for (int i = 0; i < 16; i++) {
                ulonglong2 q0 = h0[i], q1 = h1[i], q2 = h2[i], q3 = h3[i];
                fma2(a[0], q0.x, w2p[2 * i]); fma2(a[1], q0.y, w2p[2 * i + 1]);
                fma2(a[2], q1.x, w2p[2 * i]); fma2(a[3], q1.y, w2p[2 * i + 1]);
                fma2(a[4], q2.x, w2p[2 * i]); fma2(a[5], q2.y, w2p[2 * i + 1]);
                fma2(a[6], q3.x, w2p[2 * i]); fma2(a[7], q3.y, w2p[2 * i + 1]);
            }
        }
        float a2[4], s[4], q[4];
#pragma unroll
        for (int j = 0; j < 4; j++) {
            float2 s0 = unpack2(a[2 * j]), s1 = unpack2(a[2 * j + 1]);
            a2[j] = s0.x + s0.y + s1.x + s1.y + b2r;
            s[j] = a2[j]; q[j] = a2[j] * a2[j];
        }
        // LN reductions, 4 rows interleaved
#pragma unroll
        for (int o = 16; o; o >>= 1) {
#pragma unroll
            for (int j = 0; j < 4; j++) {
                s[j] += __shfl_xor_sync(0xFFFFFFFFu, s[j], o);
                q[j] += __shfl_xor_sync(0xFFFFFFFFu, q[j], o);
            }
        }
        if (lane == 0) {
#pragma unroll
            for (int j = 0; j < 4; j++) {
                red[j][warp * 2] = s[j]; red[j][warp * 2 + 1] = q[j];
            }
        }
        __syncthreads();
#pragma unroll
        for (int j = 0; j < 4; j++) {
            if (v + j < V) {
                float st  = red[j][4 * b + 0] + red[j][4 * b + 2];
                float sqt = red[j][4 * b + 1] + red[j][4 * b + 3];
                float mu  = st * (1.f / 64.f);
                float var = sqt * (1.f / 64.f) - mu * mu;
                ob[(v + j) * 64 + dq] =
                    (a2[j] - mu) * rsqrtf(var + LN_EPS) * lnwr + lnbr + xva[j];
            }
        }
        // next-iter hsA writes safe: all reads precede the barrier above.
    }
}

// ---------------- launch ----------------
extern "C" void kernel_launch(void* const* d_in, const int* in_sizes, int n_in,
                              void* d_out, int out_size) {
    const float* x    = (const float*)d_in[0];
    const float* z    = (const float*)d_in[1];
    const int*   ei   = (const int*)  d_in[2];
    // d_in[3] = r_index (unused by reference)
    const float* Wz   = (const float*)d_in[4];
    const float* bz   = (const float*)d_in[5];
    const float* W1   = (const float*)d_in[6];
    const float* b1   = (const float*)d_in[7];
    const float* W2   = (const float*)d_in[8];
    const float* b2   = (const float*)d_in[9];
    const float* beta = (const float*)d_in[10];
    const float* lnw  = (const float*)d_in[11];
    const float* lnb  = (const float*)d_in[12];
    float* out = (float*)d_out;

    int E = in_sizes[2] / 3;
    int V = in_sizes[0] / (Bc * Dc);
    int NB = (V + 255) / 256;          // 79 (must be <= 148 for resident spin)
    int NC = (E + 1023) / 1024;        // count blocks (625)
    int N4 = (Bc * V * Dc) / 4;        // float4 count for x->half (1.28M)
    int XC = (N4 + 2047) / 2048;       // convert blocks (625)

    rel_count_kernel<<<64 + NC + XC, 256>>>(z, Wz, bz, ei, E, x, N4, NC);
    scan_lookback<<<NB, 256>>>(V, E, NB);
    scatter_kernel<<<(E + 255) / 256, 256>>>(ei, E);

    cudaFuncSetAttribute((const void*)agg_kernel,
                         cudaFuncAttributeMaxDynamicSharedMemorySize, 65536);
    agg_kernel<<<296, 1024, 65536>>>(V);

    mlp_kernel<<<148, 256>>>(x, W1, b1, W2, b2, beta, lnw, lnb, out, V);
}

// round 9
// speedup vs baseline: 1.9036x; 1.0271x over previous
#include <cuda_runtime.h>
#include <cuda_fp16.h>
#include <cuda_bf16.h>

// Shapes (fixed for this problem): B=4, V=20000, D=64, R=64, E=640000
#define Bc   4
#define Dc   64
#define Rc   64
#define BD   256          // B*D
#define VMAX 20000
#define EMAX 640000
#define LN_EPS 1e-5f
#define PGRID 296         // prep grid; must be all-resident (2 blocks/SM)

// ---------------- device scratch (no allocations allowed) ----------------
__device__ float  g_rel[Rc * BD];            // relation[r][b*64+d] (64 KB)
__device__ int    g_cnt[VMAX + 1];           // zero-init; re-zeroed in scan phase
__device__ int    g_off[VMAX + 1];
__device__ int    g_cur[VMAX];
__device__ __align__(16) int g_elist[EMAX];  // packed: src | (etype<<16)
__device__ float  g_agg[(size_t)VMAX * BD];  // 20 MB
__device__ __align__(16) __half g_xh[(size_t)VMAX * BD]; // fp16 x, TRANSPOSED [v][b*64+d]
__device__ int    g_tpart[256];              // lookback: tile aggregate + 1
__device__ int    g_tincl[256];              // lookback: tile inclusive + 1
__device__ int    g_done1, g_done2;          // grid barrier counters (reset by agg)

// ---------------- helpers ----------------
__device__ __forceinline__ void fma2(unsigned long long &d,
                                     unsigned long long a,
                                     unsigned long long b) {
    asm("fma.rn.f32x2 %0, %1, %2, %0;" : "+l"(d) : "l"(a), "l"(b));
}
__device__ __forceinline__ float2 unpack2(unsigned long long v) {
    float lo, hi;
    asm("mov.b64 {%0, %1}, %2;" : "=f"(lo), "=f"(hi) : "l"(v));
    return make_float2(lo, hi);
}
__device__ __forceinline__ int ldacq(const int* p) {
    int v;
    asm volatile("ld.acquire.gpu.s32 %0, [%1];" : "=r"(v) : "l"(p));
    return v;
}
__device__ __forceinline__ void strel(int* p, int v) {
    asm volatile("st.release.gpu.s32 [%0], %1;" :: "l"(p), "r"(v) : "memory");
}
__device__ __forceinline__ void grid_barrier(int* ctr, int target) {
    __syncthreads();
    if (threadIdx.x == 0) {
        __threadfence();
        atomicAdd(ctr, 1);
        while (ldacq(ctr) < target) { }
    }
    __syncthreads();
}

// =====================================================================
// kernel 1 (prep): rel GEMM + dst histogram + x->fp16 transpose
//                  -> grid barrier -> lookback scan -> barrier -> scatter
// grid = PGRID blocks x 256 (all resident: 2/SM)
// =====================================================================
__global__ void __launch_bounds__(256, 2) prep_kernel(
    const float* __restrict__ z,  const float* __restrict__ Wz,
    const float* __restrict__ bz, const int* __restrict__ ei, int E,
    const float* __restrict__ x,  int V, int N4, int NC, int XC, int NB)
{
    __shared__ float zs[BD];
    __shared__ float wzt[64 * 65];
    int t = threadIdx.x;
    int TU = 64 + NC + XC;

    // ---- phase 1: striped work units ----
    for (int u = blockIdx.x; u < TU; u += gridDim.x) {
        if (u < 64) {
            int r = u;
            zs[t] = z[t];
            for (int idx = t; idx < 64 * 64; idx += 256) {
                int dd = idx >> 6, k = idx & 63;
                wzt[k * 65 + dd] = Wz[(r * 64 + dd) * 64 + k];
            }
            __syncthreads();
            int b = t >> 6, d = t & 63;
            float acc = bz[r * 64 + d];
#pragma unroll
            for (int k = 0; k < 64; k++)
                acc = fmaf(zs[b * 64 + k], wzt[k * 65 + d], acc);
            g_rel[r * BD + t] = acc;
        } else if (u < 64 + NC) {
            int base = (u - 64) * 1024 + t;
#pragma unroll
            for (int k = 0; k < 4; k++) {
                int e = base + k * 256;
                if (e < E) atomicAdd(&g_cnt[ei[e * 3 + 2]], 1);
            }
        } else {
            // x (fp32 [b][v][d]) -> g_xh (fp16 TRANSPOSED [v][b*64+d])
            int base = (u - 64 - NC) * 2048 + t;
            const float4* src = (const float4*)x;
#pragma unroll
            for (int k = 0; k < 8; k++) {
                int idx = base + k * 256;       // float4 index
                if (idx < N4) {
                    float4 f = src[idx];
                    int d4   = idx & 15;        // which 4-dim group
                    int rest = idx >> 4;
                    int v    = rest % VMAX;
                    int b    = rest / VMAX;
                    __half2 h01 = __floats2half2_rn(f.x, f.y);
                    __half2 h23 = __floats2half2_rn(f.z, f.w);
                    uint2 o;
                    o.x = *(unsigned*)&h01;
                    o.y = *(unsigned*)&h23;
                    *(uint2*)(g_xh + (size_t)v * BD + b * 64 + d4 * 4) = o;
                }
            }
        }
    }

    grid_barrier(&g_done1, gridDim.x);

    // ---- phase 2: decoupled-lookback exclusive scan (blocks 0..NB-1) ----
    if (blockIdx.x < NB) {
        __shared__ int ws[8];
        __shared__ int s_base;
        int lane = t & 31, w = t >> 5, bid = blockIdx.x;
        int i = bid * 256 + t;
        int c = (i < V) ? g_cnt[i] : 0;

        int inc = c;
#pragma unroll
        for (int o = 1; o < 32; o <<= 1) {
            int u2 = __shfl_up_sync(0xFFFFFFFFu, inc, o);
            if (lane >= o) inc += u2;
        }
        if (lane == 31) ws[w] = inc;
        __syncthreads();

        if (w == 0) {
            int v8 = (lane < 8) ? ws[lane] : 0;
            int sc = v8;
#pragma unroll
            for (int o = 1; o < 8; o <<= 1) {
                int u2 = __shfl_up_sync(0xFFFFFFFFu, sc, o);
                if (lane >= o) sc += u2;
            }
            int total = __shfl_sync(0xFFFFFFFFu, sc, 7);
            if (lane < 8) ws[lane] = sc - v8;
            if (lane == 0) strel(&g_tpart[bid], total + 1);

            int base = 0;
            int j = bid - 1;
            while (j >= 0) {
                int idx = j - lane;
                int iv = 0, pv = 0;
                if (idx >= 0) {
                    iv = ldacq(&g_tincl[idx]);
                    pv = ldacq(&g_tpart[idx]);
                }
                unsigned mi = __ballot_sync(0xFFFFFFFFu, iv != 0);
                unsigned mp = __ballot_sync(0xFFFFFFFFu, pv != 0);
                if (mi) {
                    int li = __ffs(mi) - 1;
                    unsigned need = (li == 0) ? 0u : ((1u << li) - 1u);
                    if ((mp & need) == need) {
                        int contrib = 0;
                        if (lane < li) contrib = pv - 1;
                        else if (lane == li) contrib = iv - 1;
#pragma unroll
                        for (int o = 16; o; o >>= 1)
                            contrib += __shfl_xor_sync(0xFFFFFFFFu, contrib, o);
                        base += contrib;
                        break;
                    }
                } else {
                    int wcount = (j + 1 < 32) ? (j + 1) : 32;
                    unsigned needall = (wcount == 32) ? 0xFFFFFFFFu
                                                      : ((1u << wcount) - 1u);
                    if ((mp & needall) == needall) {
                        int contrib = (idx >= 0) ? (pv - 1) : 0;
#pragma unroll
                        for (int o = 16; o; o >>= 1)
                            contrib += __shfl_xor_sync(0xFFFFFFFFu, contrib, o);
                        base += contrib;
                        j -= wcount;
                    }
                }
            }
            if (lane == 0) {
                s_base = base;
                strel(&g_tincl[bid], base + total + 1);
            }
        }
        __syncthreads();

        int base = s_base;
        if (i < V) {
            int excl = base + ws[w] + inc - c;
            g_off[i] = excl;
            g_cur[i] = excl;
            g_cnt[i] = 0;      // reset for next replay
        }
        if (bid == 0 && t == 0) g_off[V] = E;
    }

    grid_barrier(&g_done2, gridDim.x);

    // ---- phase 3: scatter ----
    for (int e = blockIdx.x * 256 + t; e < E; e += gridDim.x * 256) {
        int src = ei[e * 3 + 0];
        int et  = ei[e * 3 + 1];
        int dst = ei[e * 3 + 2];
        int p = atomicAdd(&g_cur[dst], 1);
        g_elist[p] = src | (et << 16);
    }
}

// =====================================================================
// kernel 2: aggregation. 1024 thr = 32 dst rows x 32 lanes, 2 blocks/SM.
// Transposed fp16 node rows (512B contiguous) + fp16 rel in smem (32 KB).
// Also resets prep's sync state for the next graph replay.
// =====================================================================
__global__ void __launch_bounds__(1024, 2) agg_kernel(int V) {
    if (blockIdx.x == 0) {
        if (threadIdx.x < 256) { g_tpart[threadIdx.x] = 0; g_tincl[threadIdx.x] = 0; }
        if (threadIdx.x == 0)  { g_done1 = 0; g_done2 = 0; }
    }
    extern __shared__ __half rel_h[];   // 64 ets x 256 halfs = 32 KB
    for (int i = threadIdx.x; i < (Rc * BD) / 2; i += blockDim.x) {
        float2 f = ((const float2*)g_rel)[i];
        ((__half2*)rel_h)[i] = __floats2half2_rn(f.x, f.y);
    }
    __syncthreads();

    int ty = threadIdx.x >> 5;          // row slot 0..31
    int lane = threadIdx.x & 31;        // owns dims [lane*8, +8) of the 256-vector
    const __half* xh = g_xh + lane * 8;
    const __half* rl = rel_h + lane * 8;

    for (int v = blockIdx.x * 32 + ty; v < V; v += gridDim.x * 32) {
        int s = g_off[v], e = g_off[v + 1];
        float a0 = 0.f, a1 = 0.f, a2 = 0.f, a3 = 0.f,
              a4 = 0.f, a5 = 0.f, a6 = 0.f, a7 = 0.f;
        int i = s;
        for (; i < e && (i & 3); i++) {
            int p = g_elist[i];
            uint4 nh = *(const uint4*)(xh + (size_t)(p & 0xFFFF) * BD);
            uint4 rh = *(const uint4*)(rl + (p >> 16) * BD);
            float2 n, r;
            n = __half22float2(*(__half2*)&nh.x); r = __half22float2(*(__half2*)&rh.x);
            a0 = fmaf(n.x, r.x, a0); a1 = fmaf(n.y, r.y, a1);
            n = __half22float2(*(__half2*)&nh.y); r = __half22float2(*(__half2*)&rh.y);
            a2 = fmaf(n.x, r.x, a2); a3 = fmaf(n.y, r.y, a3);
            n = __half22float2(*(__half2*)&nh.z); r = __half22float2(*(__half2*)&rh.z);
            a4 = fmaf(n.x, r.x, a4); a5 = fmaf(n.y, r.y, a5);
            n = __half22float2(*(__half2*)&nh.w); r = __half22float2(*(__half2*)&rh.w);
            a6 = fmaf(n.x, r.x, a6); a7 = fmaf(n.y, r.y, a7);
        }
        for (; i + 4 <= e; i += 4) {
            int4 p4 = *(const int4*)(g_elist + i);
#pragma unroll
            for (int k = 0; k < 4; k++) {
                int p = (k == 0) ? p4.x : (k == 1) ? p4.y : (k == 2) ? p4.z : p4.w;
                uint4 nh = *(const uint4*)(xh + (size_t)(p & 0xFFFF) * BD);
                uint4 rh = *(const uint4*)(rl + (p >> 16) * BD);
                float2 n, r;
                n = __half22float2(*(__half2*)&nh.x); r = __half22float2(*(__half2*)&rh.x);
                a0 = fmaf(n.x, r.x, a0); a1 = fmaf(n.y, r.y, a1);
                n = __half22float2(*(__half2*)&nh.y); r = __half22float2(*(__half2*)&rh.y);
                a2 = fmaf(n.x, r.x, a2); a3 = fmaf(n.y, r.y, a3);
                n = __half22float2(*(__half2*)&nh.z); r = __half22float2(*(__half2*)&rh.z);
                a4 = fmaf(n.x, r.x, a4); a5 = fmaf(n.y, r.y, a5);
                n = __half22float2(*(__half2*)&nh.w); r = __half22float2(*(__half2*)&rh.w);
                a6 = fmaf(n.x, r.x, a6); a7 = fmaf(n.y, r.y, a7);
            }
        }
        for (; i < e; i++) {
            int p = g_elist[i];
            uint4 nh = *(const uint4*)(xh + (size_t)(p & 0xFFFF) * BD);
            uint4 rh = *(const uint4*)(rl + (p >> 16) * BD);
            float2 n, r;
            n = __half22float2(*(__half2*)&nh.x); r = __half22float2(*(__half2*)&rh.x);
            a0 = fmaf(n.x, r.x, a0); a1 = fmaf(n.y, r.y, a1);
            n = __half22float2(*(__half2*)&nh.y); r = __half22float2(*(__half2*)&rh.y);
            a2 = fmaf(n.x, r.x, a2); a3 = fmaf(n.y, r.y, a3);
            n = __half22float2(*(__half2*)&nh.z); r = __half22float2(*(__half2*)&rh.z);
            a4 = fmaf(n.x, r.x, a4); a5 = fmaf(n.y, r.y, a5);
            n = __half22float2(*(__half2*)&nh.w); r = __half22float2(*(__half2*)&rh.w);
            a6 = fmaf(n.x, r.x, a6); a7 = fmaf(n.y, r.y, a7);
        }
        float* op = g_agg + (size_t)v * BD + lane * 8;
        *(float4*)(op)     = make_float4(a0, a1, a2, a3);
        *(float4*)(op + 4) = make_float4(a4, a5, a6, a7);
    }
}

// =====================================================================
// kernel 3: MLP (+beta*x, ReLU, LN, +x residual), 4 rows per barrier cycle
// =====================================================================
__global__ void __launch_bounds__(256) mlp_kernel(
    const float* __restrict__ x,
    const float* __restrict__ W1, const float* __restrict__ b1,
    const float* __restrict__ W2, const float* __restrict__ b2,
    const float* __restrict__ beta,
    const float* __restrict__ lnw, const float* __restrict__ lnb,
    float* __restrict__ out, int V)
{
    __shared__ __align__(16) float hsA[4][BD];
    __shared__ __align__(16) float hsB[4][BD];
    __shared__ float red[4][16];
    int t = threadIdx.x;
    int b = t >> 6, dq = t & 63;
    int warp = t >> 5, lane = t & 31;

    unsigned long long w1p[32], w2p[32];
    {
        const unsigned long long* W1q = (const unsigned long long*)(W1 + dq * 64);
        const unsigned long long* W2q = (const unsigned long long*)(W2 + dq * 64);
#pragma unroll
        for (int i = 0; i < 32; i++) { w1p[i] = W1q[i]; w2p[i] = W2q[i]; }
    }
    float b1r = b1[dq], b2r = b2[dq];
    float betar = beta[dq], lnwr = lnw[dq], lnbr = lnb[dq];

    const float* xb = x + (size_t)b * V * 64;
    float*       ob = out + (size_t)b * V * 64;

    int stride = gridDim.x * 4;
    int v0 = blockIdx.x * 4;
    float xvn[4], agn[4];
#pragma unroll
    for (int j = 0; j < 4; j++) {
        int vv = v0 + j;
        if (vv < V) { xvn[j] = xb[vv * 64 + dq]; agn[j] = g_agg[(size_t)vv * BD + t]; }
        else        { xvn[j] = 0.f;              agn[j] = 0.f; }
    }

    for (int v = v0; v < V; v += stride) {
        float xva[4];
#pragma unroll
        for (int j = 0; j < 4; j++) {
            xva[j] = xvn[j];
            hsA[j][t] = agn[j] + betar * xva[j];
        }
        int vn = v + stride;
#pragma unroll
        for (int j = 0; j < 4; j++) {
            int vv = vn + j;
            if (vv < V) { xvn[j] = xb[vv * 64 + dq]; agn[j] = g_agg[(size_t)vv * BD + t]; }
        }
        __syncthreads();

        unsigned long long a[8];
#pragma unroll
        for (int j = 0; j < 8; j++) a[j] = 0ull;
        {
            const ulonglong2* h0 = (const ulonglong2*)(hsA[0] + (b << 6));
            const ulonglong2* h1 = (const ulonglong2*)(hsA[1] + (b << 6));
            const ulonglong2* h2 = (const ulonglong2*)(hsA[2] + (b << 6));
            const ulonglong2* h3 = (const ulonglong2*)(hsA[3] + (b << 6));
#pragma unroll
            for (int i = 0; i < 16; i++) {
                ulonglong2 q0 = h0[i], q1 = h1[i], q2 = h2[i], q3 = h3[i];
                fma2(a[0], q0.x, w1p[2 * i]); fma2(a[1], q0.y, w1p[2 * i + 1]);
                fma2(a[2], q1.x, w1p[2 * i]); fma2(a[3], q1.y, w1p[2 * i + 1]);
                fma2(a[4], q2.x, w1p[2 * i]); fma2(a[5], q2.y, w1p[2 * i + 1]);
                fma2(a[6], q3.x, w1p[2 * i]); fma2(a[7], q3.y, w1p[2 * i + 1]);
            }
        }
#pragma unroll
        for (int j = 0; j < 4; j++) {
            float2 s0 = unpack2(a[2 * j]), s1 = unpack2(a[2 * j + 1]);
            hsB[j][t] = fmaxf(s0.x + s0.y + s1.x + s1.y + b1r, 0.f);
        }
        __syncthreads();

#pragma unroll
        for (int j = 0; j < 8; j++) a[j] = 0ull;
        {
            const ulonglong2* h0 = (const ulonglong2*)(hsB[0] + (b << 6));
            const ulonglong2* h1 = (const ulonglong2*)(hsB[1] + (b << 6));
            const ulonglong2* h2 = (const ulonglong2*)(hsB[2] + (b << 6));
            const ulonglong2* h3 = (const ulonglong2*)(hsB[3] + (b << 6));
#pragma unroll
            for (int i = 0; i < 16; i++) {
                ulonglong2 q0 = h0[i], q1 = h1[i], q2 = h2[i], q3 = h3[i];
                fma2(a[0], q0.x, w2p[2 * i]); fma2(a[1], q0.y, w2p[2 * i + 1]);
                fma2(a[2], q1.x, w2p[2 * i]); fma2(a[3], q1.y, w2p[2 * i + 1]);
                fma2(a[4], q2.x, w2p[2 * i]); fma2(a[5], q2.y, w2p[2 * i + 1]);
                fma2(a[6], q3.x, w2p[2 * i]); fma2(a[7], q3.y, w2p[2 * i + 1]);
            }
        }
        float a2[4], s[4], q[4];
#pragma unroll
        for (int j = 0; j < 4; j++) {
            float2 s0 = unpack2(a[2 * j]), s1 = unpack2(a[2 * j + 1]);
            a2[j] = s0.x + s0.y + s1.x + s1.y + b2r;
            s[j] = a2[j]; q[j] = a2[j] * a2[j];
        }
#pragma unroll
        for (int o = 16; o; o >>= 1) {
#pragma unroll
            for (int j = 0; j < 4; j++) {
                s[j] += __shfl_xor_sync(0xFFFFFFFFu, s[j], o);
                q[j] += __shfl_xor_sync(0xFFFFFFFFu, q[j], o);
            }
        }
        if (lane == 0) {
#pragma unroll
            for (int j = 0; j < 4; j++) {
                red[j][warp * 2] = s[j]; red[j][warp * 2 + 1] = q[j];
            }
        }
        __syncthreads();
#pragma unroll
        for (int j = 0; j < 4; j++) {
            if (v + j < V) {
                float st  = red[j][4 * b + 0] + red[j][4 * b + 2];
                float sqt = red[j][4 * b + 1] + red[j][4 * b + 3];
                float mu  = st * (1.f / 64.f);
                float var = sqt * (1.f / 64.f) - mu * mu;
                ob[(v + j) * 64 + dq] =
                    (a2[j] - mu) * rsqrtf(var + LN_EPS) * lnwr + lnbr + xva[j];
            }
        }
    }
}

// ---------------- launch ----------------
extern "C" void kernel_launch(void* const* d_in, const int* in_sizes, int n_in,
                              void* d_out, int out_size) {
    const float* x    = (const float*)d_in[0];
    const float* z    = (const float*)d_in[1];
    const int*   ei   = (const int*)  d_in[2];
    // d_in[3] = r_index (unused by reference)
    const float* Wz   = (const float*)d_in[4];
    const float* bz   = (const float*)d_in[5];
    const float* W1   = (const float*)d_in[6];
    const float* b1   = (const float*)d_in[7];
    const float* W2   = (const float*)d_in[8];
    const float* b2   = (const float*)d_in[9];
    const float* beta = (const float*)d_in[10];
    const float* lnw  = (const float*)d_in[11];
    const float* lnb  = (const float*)d_in[12];
    float* out = (float*)d_out;

    int E = in_sizes[2] / 3;
    int V = in_sizes[0] / (Bc * Dc);
    int NB = (V + 255) / 256;          // 79 scan tiles (<= PGRID)
    int NC = (E + 1023) / 1024;        // histogram units (625)
    int N4 = (Bc * V * Dc) / 4;        // float4 count for convert (1.28M)
    int XC = (N4 + 2047) / 2048;       // convert units (625)

    prep_kernel<<<PGRID, 256>>>(z, Wz, bz, ei, E, x, V, N4, NC, XC, NB);
    agg_kernel<<<PGRID, 1024, 32768>>>(V);
    mlp_kernel<<<148, 256>>>(x, W1, b1, W2, b2, beta, lnw, lnb, out, V);
}